// round 4
// baseline (speedup 1.0000x reference)
#include <cuda_runtime.h>
#include <cstdint>

// Problem constants
#define C_DIM   384
#define N_DIM   1152
#define B_SZ    8
#define H_IMG   224
#define W_IMG   224
#define HWB     50176
#define M_TOT   401408
#define HD      96
#define NHEADS  4

// QKV scratch in natural token order: [M_TOT][1152]
__device__ float g_qkv[(size_t)M_TOT * N_DIM];

__device__ __forceinline__ uint32_t f2tf(float f) {
    uint32_t r; asm("cvt.rna.tf32.f32 %0, %1;" : "=r"(r) : "f"(f)); return r;
}

__device__ __forceinline__ void mma_tf32(float& c0, float& c1, float& c2, float& c3,
                                         uint32_t a0, uint32_t a1, uint32_t a2, uint32_t a3,
                                         uint32_t b0, uint32_t b1) {
    asm volatile(
        "mma.sync.aligned.m16n8k8.row.col.f32.tf32.tf32.f32 "
        "{%0,%1,%2,%3}, {%4,%5,%6,%7}, {%8,%9}, {%0,%1,%2,%3};"
        : "+f"(c0), "+f"(c1), "+f"(c2), "+f"(c3)
        : "r"(a0), "r"(a1), "r"(a2), "r"(a3), "r"(b0), "r"(b1));
}

// ---------------------------------------------------------------------------
// Kernel 1: QKV GEMM, tf32 mma.sync, double-buffered B + register prefetch.
//   C[128 tokens][1152 ch] = A[m][384] * W^T; A resident in SMEM (tf32),
//   B streamed in 24 k-stages of 16 per N-tile, 2 SMEM buffers, 1 sync/stage.
// ---------------------------------------------------------------------------
#define AST  136
#define BKS  16
#define BSTG (BKS * AST)                             // words per B stage
#define QKV_SMEM ((384 * AST + 2 * BSTG) * 4)        // 226,304 B

__global__ void __launch_bounds__(256, 1) qkv_mma(
    const float* __restrict__ x,
    const float* __restrict__ w,
    const float* __restrict__ bias)
{
    extern __shared__ uint32_t smu[];
    uint32_t* As = smu;                  // [384][136] tf32, [k][m]
    uint32_t* Bs = smu + 384 * AST;      // [2][16][136] tf32, [buf][k][n]

    const int tid = threadIdx.x;
    const int wid = tid >> 5;
    const int lid = tid & 31;
    const int mw  = wid & 1;             // 2 m-subtiles of 64
    const int nw  = wid >> 1;            // 4 n-subtiles of 32
    const int lq  = lid >> 2;            // 0..7
    const int lr  = lid & 3;             // 0..3

    const int m0 = blockIdx.x * 128;     // 50176 % 128 == 0
    const int b  = m0 / HWB;
    const float* xb = x + (size_t)b * C_DIM * HWB + (m0 - b * HWB);

    // Prefetch-lane mapping for W stages: n fixed per thread, two k-quads
    const int pn  = tid & 127;           // n within 128-tile
    const int pk0 = (tid >> 7) * 4;      // float4 k-offset (0 or 4)  -> k = pk0.. +4
    // thread loads k-float4s pk0 and pk0+8 of the 16-k stage

    // Kick off stage-0 prefetch of N-tile 0 before the big A load
    float4 q0 = *(const float4*)(w + (size_t)pn * C_DIM + pk0);
    float4 q1 = *(const float4*)(w + (size_t)pn * C_DIM + pk0 + 8);

    // ---- Load A once: 384 k-rows x 128 tokens, STS.128, coalesced over m ----
    for (int i = tid; i < 12288; i += 256) {          // 12288 float4
        int k = i >> 5, m4 = i & 31;
        float4 v = *(const float4*)(xb + (size_t)k * HWB + m4 * 4);
        *(uint4*)(As + k * AST + m4 * 4) =
            make_uint4(f2tf(v.x), f2tf(v.y), f2tf(v.z), f2tf(v.w));
    }

    for (int nt = 0; nt < 9; ++nt) {
        const int n0 = nt * 128;

        // Stage-0 STS (data prefetched during previous tile / A load)
        {
            uint32_t* d = Bs + pk0 * AST + pn;
            d[0 * AST] = f2tf(q0.x); d[1 * AST] = f2tf(q0.y);
            d[2 * AST] = f2tf(q0.z); d[3 * AST] = f2tf(q0.w);
            uint32_t* d2 = d + 8 * AST;
            d2[0 * AST] = f2tf(q1.x); d2[1 * AST] = f2tf(q1.y);
            d2[2 * AST] = f2tf(q1.z); d2[3 * AST] = f2tf(q1.w);
        }
        __syncthreads();

        float c[4][4][4];
        #pragma unroll
        for (int i = 0; i < 4; ++i)
            #pragma unroll
            for (int j = 0; j < 4; ++j)
                c[i][j][0] = c[i][j][1] = c[i][j][2] = c[i][j][3] = 0.f;

        for (int s = 0; s < 24; ++s) {
            // ---- Prefetch next stage (or next tile's stage 0) ----
            if (s < 23) {
                const float* wp = w + (size_t)(n0 + pn) * C_DIM + (s + 1) * BKS + pk0;
                q0 = *(const float4*)wp;
                q1 = *(const float4*)(wp + 8);
            } else if (nt < 8) {
                const float* wp = w + (size_t)(n0 + 128 + pn) * C_DIM + pk0;
                q0 = *(const float4*)wp;
                q1 = *(const float4*)(wp + 8);
            }

            // ---- Compute stage s from buf (s & 1): 2 k-chunks of 8 ----
            const uint32_t* Bb = Bs + (s & 1) * BSTG;
            uint32_t a[2][4][4], bb[2][4][2];
            #pragma unroll
            for (int kc = 0; kc < 2; ++kc) {
                const int kA = s * 16 + kc * 8 + lr;
                const int kB = kc * 8 + lr;
                #pragma unroll
                for (int i = 0; i < 4; ++i) {
                    int r = mw * 64 + i * 16 + lq;
                    a[kc][i][0] = As[kA * AST + r];
                    a[kc][i][1] = As[kA * AST + r + 8];
                    a[kc][i][2] = As[(kA + 4) * AST + r];
                    a[kc][i][3] = As[(kA + 4) * AST + r + 8];
                }
                #pragma unroll
                for (int j = 0; j < 4; ++j) {
                    int n = nw * 32 + j * 8 + lq;
                    bb[kc][j][0] = Bb[kB * AST + n];
                    bb[kc][j][1] = Bb[(kB + 4) * AST + n];
                }
            }
            #pragma unroll
            for (int kc = 0; kc < 2; ++kc)
                #pragma unroll
                for (int i = 0; i < 4; ++i)
                    #pragma unroll
                    for (int j = 0; j < 4; ++j)
                        mma_tf32(c[i][j][0], c[i][j][1], c[i][j][2], c[i][j][3],
                                 a[kc][i][0], a[kc][i][1], a[kc][i][2], a[kc][i][3],
                                 bb[kc][j][0], bb[kc][j][1]);

            // ---- Store prefetched stage into the other buffer ----
            if (s < 23) {
                uint32_t* d = Bs + ((s + 1) & 1) * BSTG + pk0 * AST + pn;
                d[0 * AST] = f2tf(q0.x); d[1 * AST] = f2tf(q0.y);
                d[2 * AST] = f2tf(q0.z); d[3 * AST] = f2tf(q0.w);
                uint32_t* d2 = d + 8 * AST;
                d2[0 * AST] = f2tf(q1.x); d2[1 * AST] = f2tf(q1.y);
                d2[2 * AST] = f2tf(q1.z); d2[3 * AST] = f2tf(q1.w);
            }
            __syncthreads();
        }

        // ---- Epilogue: bias + float2 stores (regs only, no smem) ----
        #pragma unroll
        for (int j = 0; j < 4; ++j) {
            const int gn = n0 + nw * 32 + j * 8 + lr * 2;
            float2 bv = *(const float2*)(bias + gn);
            #pragma unroll
            for (int i = 0; i < 4; ++i) {
                const int gm0 = m0 + mw * 64 + i * 16 + lq;
                float2 v0 = make_float2(c[i][j][0] + bv.x, c[i][j][1] + bv.y);
                float2 v1 = make_float2(c[i][j][2] + bv.x, c[i][j][3] + bv.y);
                *(float2*)(g_qkv + (size_t)gm0 * N_DIM + gn)       = v0;
                *(float2*)(g_qkv + (size_t)(gm0 + 8) * N_DIM + gn) = v1;
            }
        }
    }
}

// ---------------------------------------------------------------------------
// Kernel 2: windowed attention (unchanged from Round 3)
// ---------------------------------------------------------------------------
#define SD   52
#define VST  100
#define SCST 52
#define ATTN_SMEM ((2 * 96 * SD + 52 * VST + 52 * SCST) * sizeof(float))

__global__ void __launch_bounds__(256) attn_kernel(float* __restrict__ out)
{
    extern __shared__ float sm[];
    float* qs = sm;
    float* ks = qs + 96 * SD;
    float* vs = ks + 96 * SD;
    float* sc = vs + 52 * VST;

    const int tid  = threadIdx.x;
    const int win  = blockIdx.x;
    const int head = blockIdx.y;
    const int b    = win >> 10;
    const int wh   = (win >> 5) & 31;
    const int ww   = win & 31;
    const float scale = 0.10206207261596577f;

    for (int e = tid; e < 3 * 96; e += 256) {
        int d = e % 96;
        int p = 49 + e / 96;
        qs[d * SD + p] = 0.f;
        ks[d * SD + p] = 0.f;
    }

    for (int e = tid; e < 49 * 96; e += 256) {
        int d = e % 96;
        int p = e / 96;
        int ph = p / 7;
        int h  = wh * 7 + ph;
        int wc = ww * 7 + (p - ph * 7);
        const float* row = g_qkv + ((size_t)b * HWB + h * W_IMG + wc) * N_DIM + head * HD;
        qs[d * SD + p] = row[d] * scale;
        ks[d * SD + p] = row[C_DIM + d];
        vs[p * VST + d] = row[2 * C_DIM + d];
    }
    __syncthreads();

    if (tid < 169) {
        const int ti = (tid % 13) * 4;
        const int tj = (tid / 13) * 4;
        float acc[4][4] = {};
        for (int d = 0; d < 96; d++) {
            float4 qv = *(const float4*)(qs + d * SD + ti);
            float4 kv = *(const float4*)(ks + d * SD + tj);
            acc[0][0] += qv.x * kv.x; acc[0][1] += qv.x * kv.y;
            acc[0][2] += qv.x * kv.z; acc[0][3] += qv.x * kv.w;
            acc[1][0] += qv.y * kv.x; acc[1][1] += qv.y * kv.y;
            acc[1][2] += qv.y * kv.z; acc[1][3] += qv.y * kv.w;
            acc[2][0] += qv.z * kv.x; acc[2][1] += qv.z * kv.y;
            acc[2][2] += qv.z * kv.z; acc[2][3] += qv.z * kv.w;
            acc[3][0] += qv.w * kv.x; acc[3][1] += qv.w * kv.y;
            acc[3][2] += qv.w * kv.z; acc[3][3] += qv.w * kv.w;
        }
        #pragma unroll
        for (int jj = 0; jj < 4; jj++) {
            float4 v = make_float4(acc[0][jj], acc[1][jj], acc[2][jj], acc[3][jj]);
            *(float4*)(sc + (tj + jj) * SCST + ti) = v;
        }
    }
    __syncthreads();

    if (tid < 49) {
        float mx = -1e30f;
        for (int j = 0; j < 49; j++) mx = fmaxf(mx, sc[j * SCST + tid]);
        float sum = 0.f;
        for (int j = 0; j < 49; j++) {
            float ev = __expf(sc[j * SCST + tid] - mx);
            sc[j * SCST + tid] = ev;
            sum += ev;
        }
        float inv = 1.f / sum;
        for (int j = 0; j < 49; j++) sc[j * SCST + tid] *= inv;
    }
    __syncthreads();

    float* osm = qs;
    for (int tile = tid; tile < 312; tile += 256) {
        int p0 = (tile % 13) * 4;
        int d0 = (tile / 13) * 4;
        float acc[4][4] = {};
        for (int j = 0; j < 49; j++) {
            float4 av = *(const float4*)(sc + j * SCST + p0);
            float4 vv = *(const float4*)(vs + j * VST + d0);
            acc[0][0] += av.x * vv.x; acc[0][1] += av.x * vv.y;
            acc[0][2] += av.x * vv.z; acc[0][3] += av.x * vv.w;
            acc[1][0] += av.y * vv.x; acc[1][1] += av.y * vv.y;
            acc[1][2] += av.y * vv.z; acc[1][3] += av.y * vv.w;
            acc[2][0] += av.z * vv.x; acc[2][1] += av.z * vv.y;
            acc[2][2] += av.z * vv.z; acc[2][3] += av.z * vv.w;
            acc[3][0] += av.w * vv.x; acc[3][1] += av.w * vv.y;
            acc[3][2] += av.w * vv.z; acc[3][3] += av.w * vv.w;
        }
        #pragma unroll
        for (int pp = 0; pp < 4; pp++) {
            if (p0 + pp < 49) {
                float4 o4 = make_float4(acc[pp][0], acc[pp][1], acc[pp][2], acc[pp][3]);
                *(float4*)(osm + (p0 + pp) * VST + d0) = o4;
            }
        }
    }
    __syncthreads();

    for (int e = tid; e < 49 * 96; e += 256) {
        int p = e % 49;
        int d = e / 49;
        int ph = p / 7;
        int h  = wh * 7 + ph;
        int wc = ww * 7 + (p - ph * 7);
        out[(((size_t)b * C_DIM + head * HD + d) * H_IMG + h) * W_IMG + wc] =
            osm[p * VST + d];
    }
}

// ---------------------------------------------------------------------------
extern "C" void kernel_launch(void* const* d_in, const int* in_sizes, int n_in,
                              void* d_out, int out_size)
{
    const float* x    = (const float*)d_in[0];
    const float* w    = (const float*)d_in[1];
    const float* bias = (const float*)d_in[2];
    float* out        = (float*)d_out;

    cudaFuncSetAttribute(qkv_mma, cudaFuncAttributeMaxDynamicSharedMemorySize,
                         (int)QKV_SMEM);
    cudaFuncSetAttribute(attn_kernel, cudaFuncAttributeMaxDynamicSharedMemorySize,
                         (int)ATTN_SMEM);

    qkv_mma<<<M_TOT / 128, 256, QKV_SMEM>>>(x, w, bias);
    attn_kernel<<<dim3(B_SZ * 32 * 32, NHEADS), 256, ATTN_SMEM>>>(out);
}

// round 5
// speedup vs baseline: 1.3355x; 1.3355x over previous
#include <cuda_runtime.h>
#include <cstdint>

// Problem constants
#define C_DIM   384
#define N_DIM   1152
#define B_SZ    8
#define H_IMG   224
#define W_IMG   224
#define HWB     50176
#define M_TOT   401408
#define HD      96
#define NHEADS  4

// QKV scratch in natural token order: [M_TOT][1152]
__device__ float g_qkv[(size_t)M_TOT * N_DIM];

__device__ __forceinline__ uint32_t pack_h2(float lo, float hi) {
    uint32_t r;
    asm("cvt.rn.f16x2.f32 %0, %1, %2;" : "=r"(r) : "f"(hi), "f"(lo));
    return r;   // d<15:0> = lo, d<31:16> = hi
}

__device__ __forceinline__ void mma_f16(float& c0, float& c1, float& c2, float& c3,
                                        uint32_t a0, uint32_t a1, uint32_t a2, uint32_t a3,
                                        uint32_t b0, uint32_t b1) {
    asm volatile(
        "mma.sync.aligned.m16n8k16.row.col.f32.f16.f16.f32 "
        "{%0,%1,%2,%3}, {%4,%5,%6,%7}, {%8,%9}, {%0,%1,%2,%3};"
        : "+f"(c0), "+f"(c1), "+f"(c2), "+f"(c3)
        : "r"(a0), "r"(a1), "r"(a2), "r"(a3), "r"(b0), "r"(b1));
}

// ---------------------------------------------------------------------------
// Kernel 1: QKV GEMM, fp16 mma.sync m16n8k16 (fp32 accum).
//   C[128 tokens][1152 ch] = A[m][384] * W^T.
//   As[m][k] half2 words, row stride 197 words; Bs[n][k], stride 20 words.
//   Single-buffer B stages (Round-3 schedule), 2 CTAs/SM for overlap.
// ---------------------------------------------------------------------------
#define ASTW 197                                   // As row stride (words)
#define BSTW 20                                    // Bs row stride (words)
#define QKV_SMEM ((128 * ASTW + 128 * BSTW) * 4)   // 111,104 B

__global__ void __launch_bounds__(256, 2) qkv_mma(
    const float* __restrict__ x,
    const float* __restrict__ w,
    const float* __restrict__ bias)
{
    extern __shared__ uint32_t smu[];
    uint32_t* As = smu;                  // [128 m][197 w] (k-pairs)
    uint32_t* Bs = smu + 128 * ASTW;     // [128 n][20 w]

    const int tid = threadIdx.x;
    const int wid = tid >> 5;
    const int lid = tid & 31;
    const int mw  = wid & 1;             // 2 m-subtiles of 64
    const int nw  = wid >> 1;            // 4 n-subtiles of 32
    const int lq  = lid >> 2;            // 0..7
    const int lr  = lid & 3;             // 0..3

    const int m0 = blockIdx.x * 128;     // 50176 % 128 == 0
    const int b  = m0 / HWB;
    const float* xb = x + (size_t)b * C_DIM * HWB + (m0 - b * HWB);

    // ---- Prologue: transpose x[k][m] -> As[m][k-pair], coalesced LDG ----
    // i: k2 = i>>5 (k-pair 0..191), m4 = i&31 (m-quad)
    for (int i = tid; i < 6144; i += 256) {
        int k2 = i >> 5, m4 = i & 31;
        const float* p0 = xb + (size_t)(2 * k2) * HWB + m4 * 4;
        float4 v0 = *(const float4*)p0;
        float4 v1 = *(const float4*)(p0 + HWB);
        uint32_t* d = As + (m4 * 4) * ASTW + k2;
        d[0 * ASTW] = pack_h2(v0.x, v1.x);
        d[1 * ASTW] = pack_h2(v0.y, v1.y);
        d[2 * ASTW] = pack_h2(v0.z, v1.z);
        d[3 * ASTW] = pack_h2(v0.w, v1.w);
    }

    for (int nt = 0; nt < 9; ++nt) {
        const int n0 = nt * 128;
        float c[4][4][4];
        #pragma unroll
        for (int i = 0; i < 4; ++i)
            #pragma unroll
            for (int j = 0; j < 4; ++j)
                c[i][j][0] = c[i][j][1] = c[i][j][2] = c[i][j][3] = 0.f;

        for (int s = 0; s < 12; ++s) {
            __syncthreads();             // prior-stage readers done
            // ---- Load B stage: W[n0+n][s*32 .. +32) -> Bs[n][k-pair] ----
            #pragma unroll
            for (int p = 0; p < 4; ++p) {
                int idx = p * 256 + tid;
                int n = idx & 127, kq = idx >> 7;           // kq: float4 index 0..7
                float4 v = *(const float4*)(w + (size_t)(n0 + n) * C_DIM
                                            + s * 32 + kq * 4);
                uint32_t* d = Bs + n * BSTW + kq * 2;
                d[0] = pack_h2(v.x, v.y);
                d[1] = pack_h2(v.z, v.w);
            }
            __syncthreads();

            #pragma unroll
            for (int kc = 0; kc < 2; ++kc) {                // 2 chunks of k16
                const int kw = s * 16 + kc * 8;             // word offset in As
                uint32_t a[4][4], bb[4][2];
                #pragma unroll
                for (int i = 0; i < 4; ++i) {
                    const int r = mw * 64 + i * 16;
                    a[i][0] = As[(r + lq) * ASTW + kw + lr];
                    a[i][1] = As[(r + 8 + lq) * ASTW + kw + lr];
                    a[i][2] = As[(r + lq) * ASTW + kw + 4 + lr];
                    a[i][3] = As[(r + 8 + lq) * ASTW + kw + 4 + lr];
                }
                #pragma unroll
                for (int j = 0; j < 4; ++j) {
                    const int n = nw * 32 + j * 8 + lq;
                    bb[j][0] = Bs[n * BSTW + kc * 8 + lr];
                    bb[j][1] = Bs[n * BSTW + kc * 8 + 4 + lr];
                }
                #pragma unroll
                for (int i = 0; i < 4; ++i)
                    #pragma unroll
                    for (int j = 0; j < 4; ++j)
                        mma_f16(c[i][j][0], c[i][j][1], c[i][j][2], c[i][j][3],
                                a[i][0], a[i][1], a[i][2], a[i][3],
                                bb[j][0], bb[j][1]);
            }
        }

        // ---- Epilogue: bias + float2 stores ----
        #pragma unroll
        for (int j = 0; j < 4; ++j) {
            const int gn = n0 + nw * 32 + j * 8 + lr * 2;
            float2 bv = *(const float2*)(bias + gn);
            #pragma unroll
            for (int i = 0; i < 4; ++i) {
                const int gm0 = m0 + mw * 64 + i * 16 + lq;
                float2 v0 = make_float2(c[i][j][0] + bv.x, c[i][j][1] + bv.y);
                float2 v1 = make_float2(c[i][j][2] + bv.x, c[i][j][3] + bv.y);
                *(float2*)(g_qkv + (size_t)gm0 * N_DIM + gn)       = v0;
                *(float2*)(g_qkv + (size_t)(gm0 + 8) * N_DIM + gn) = v1;
            }
        }
    }
}

// ---------------------------------------------------------------------------
// Kernel 2: windowed attention (unchanged from Round 3)
// ---------------------------------------------------------------------------
#define SD   52
#define VST  100
#define SCST 52
#define ATTN_SMEM ((2 * 96 * SD + 52 * VST + 52 * SCST) * sizeof(float))

__global__ void __launch_bounds__(256) attn_kernel(float* __restrict__ out)
{
    extern __shared__ float sm[];
    float* qs = sm;
    float* ks = qs + 96 * SD;
    float* vs = ks + 96 * SD;
    float* sc = vs + 52 * VST;

    const int tid  = threadIdx.x;
    const int win  = blockIdx.x;
    const int head = blockIdx.y;
    const int b    = win >> 10;
    const int wh   = (win >> 5) & 31;
    const int ww   = win & 31;
    const float scale = 0.10206207261596577f;

    for (int e = tid; e < 3 * 96; e += 256) {
        int d = e % 96;
        int p = 49 + e / 96;
        qs[d * SD + p] = 0.f;
        ks[d * SD + p] = 0.f;
    }

    for (int e = tid; e < 49 * 96; e += 256) {
        int d = e % 96;
        int p = e / 96;
        int ph = p / 7;
        int h  = wh * 7 + ph;
        int wc = ww * 7 + (p - ph * 7);
        const float* row = g_qkv + ((size_t)b * HWB + h * W_IMG + wc) * N_DIM + head * HD;
        qs[d * SD + p] = row[d] * scale;
        ks[d * SD + p] = row[C_DIM + d];
        vs[p * VST + d] = row[2 * C_DIM + d];
    }
    __syncthreads();

    if (tid < 169) {
        const int ti = (tid % 13) * 4;
        const int tj = (tid / 13) * 4;
        float acc[4][4] = {};
        for (int d = 0; d < 96; d++) {
            float4 qv = *(const float4*)(qs + d * SD + ti);
            float4 kv = *(const float4*)(ks + d * SD + tj);
            acc[0][0] += qv.x * kv.x; acc[0][1] += qv.x * kv.y;
            acc[0][2] += qv.x * kv.z; acc[0][3] += qv.x * kv.w;
            acc[1][0] += qv.y * kv.x; acc[1][1] += qv.y * kv.y;
            acc[1][2] += qv.y * kv.z; acc[1][3] += qv.y * kv.w;
            acc[2][0] += qv.z * kv.x; acc[2][1] += qv.z * kv.y;
            acc[2][2] += qv.z * kv.z; acc[2][3] += qv.z * kv.w;
            acc[3][0] += qv.w * kv.x; acc[3][1] += qv.w * kv.y;
            acc[3][2] += qv.w * kv.z; acc[3][3] += qv.w * kv.w;
        }
        #pragma unroll
        for (int jj = 0; jj < 4; jj++) {
            float4 v = make_float4(acc[0][jj], acc[1][jj], acc[2][jj], acc[3][jj]);
            *(float4*)(sc + (tj + jj) * SCST + ti) = v;
        }
    }
    __syncthreads();

    if (tid < 49) {
        float mx = -1e30f;
        for (int j = 0; j < 49; j++) mx = fmaxf(mx, sc[j * SCST + tid]);
        float sum = 0.f;
        for (int j = 0; j < 49; j++) {
            float ev = __expf(sc[j * SCST + tid] - mx);
            sc[j * SCST + tid] = ev;
            sum += ev;
        }
        float inv = 1.f / sum;
        for (int j = 0; j < 49; j++) sc[j * SCST + tid] *= inv;
    }
    __syncthreads();

    float* osm = qs;
    for (int tile = tid; tile < 312; tile += 256) {
        int p0 = (tile % 13) * 4;
        int d0 = (tile / 13) * 4;
        float acc[4][4] = {};
        for (int j = 0; j < 49; j++) {
            float4 av = *(const float4*)(sc + j * SCST + p0);
            float4 vv = *(const float4*)(vs + j * VST + d0);
            acc[0][0] += av.x * vv.x; acc[0][1] += av.x * vv.y;
            acc[0][2] += av.x * vv.z; acc[0][3] += av.x * vv.w;
            acc[1][0] += av.y * vv.x; acc[1][1] += av.y * vv.y;
            acc[1][2] += av.y * vv.z; acc[1][3] += av.y * vv.w;
            acc[2][0] += av.z * vv.x; acc[2][1] += av.z * vv.y;
            acc[2][2] += av.z * vv.z; acc[2][3] += av.z * vv.w;
            acc[3][0] += av.w * vv.x; acc[3][1] += av.w * vv.y;
            acc[3][2] += av.w * vv.z; acc[3][3] += av.w * vv.w;
        }
        #pragma unroll
        for (int pp = 0; pp < 4; pp++) {
            if (p0 + pp < 49) {
                float4 o4 = make_float4(acc[pp][0], acc[pp][1], acc[pp][2], acc[pp][3]);
                *(float4*)(osm + (p0 + pp) * VST + d0) = o4;
            }
        }
    }
    __syncthreads();

    for (int e = tid; e < 49 * 96; e += 256) {
        int p = e % 49;
        int d = e / 49;
        int ph = p / 7;
        int h  = wh * 7 + ph;
        int wc = ww * 7 + (p - ph * 7);
        out[(((size_t)b * C_DIM + head * HD + d) * H_IMG + h) * W_IMG + wc] =
            osm[p * VST + d];
    }
}

// ---------------------------------------------------------------------------
extern "C" void kernel_launch(void* const* d_in, const int* in_sizes, int n_in,
                              void* d_out, int out_size)
{
    const float* x    = (const float*)d_in[0];
    const float* w    = (const float*)d_in[1];
    const float* bias = (const float*)d_in[2];
    float* out        = (float*)d_out;

    cudaFuncSetAttribute(qkv_mma, cudaFuncAttributeMaxDynamicSharedMemorySize,
                         (int)QKV_SMEM);
    cudaFuncSetAttribute(attn_kernel, cudaFuncAttributeMaxDynamicSharedMemorySize,
                         (int)ATTN_SMEM);

    qkv_mma<<<M_TOT / 128, 256, QKV_SMEM>>>(x, w, bias);
    attn_kernel<<<dim3(B_SZ * 32 * 32, NHEADS), 256, ATTN_SMEM>>>(out);
}

// round 6
// speedup vs baseline: 1.8673x; 1.3982x over previous
#include <cuda_runtime.h>
#include <cstdint>

// Problem constants
#define C_DIM   384
#define N_DIM   1152
#define B_SZ    8
#define H_IMG   224
#define W_IMG   224
#define HWB     50176
#define M_TOT   401408
#define HD      96
#define NHEADS  4

// QKV scratch in natural token order: [M_TOT][1152]
__device__ float g_qkv[(size_t)M_TOT * N_DIM];
// Pre-converted W in fp16 (half2 words): [1152][384] halves = 221184 words
__device__ uint32_t g_wh[221184];

__device__ __forceinline__ uint32_t pack_h2(float lo, float hi) {
    uint32_t r;
    asm("cvt.rn.f16x2.f32 %0, %1, %2;" : "=r"(r) : "f"(hi), "f"(lo));
    return r;   // d<15:0> = lo, d<31:16> = hi
}

__device__ __forceinline__ uint32_t smem_u32(const void* p) {
    uint32_t a;
    asm("{ .reg .u64 t; cvta.to.shared.u64 t, %1; cvt.u32.u64 %0, t; }"
        : "=r"(a) : "l"(p));
    return a;
}

__device__ __forceinline__ void ldsm_x4(uint32_t& r0, uint32_t& r1,
                                        uint32_t& r2, uint32_t& r3, uint32_t a) {
    asm volatile("ldmatrix.sync.aligned.m8n8.x4.shared.b16 {%0,%1,%2,%3}, [%4];"
                 : "=r"(r0), "=r"(r1), "=r"(r2), "=r"(r3) : "r"(a));
}
__device__ __forceinline__ void ldsm_x4_t(uint32_t& r0, uint32_t& r1,
                                          uint32_t& r2, uint32_t& r3, uint32_t a) {
    asm volatile("ldmatrix.sync.aligned.m8n8.x4.trans.shared.b16 {%0,%1,%2,%3}, [%4];"
                 : "=r"(r0), "=r"(r1), "=r"(r2), "=r"(r3) : "r"(a));
}

__device__ __forceinline__ void mma_f16(float& c0, float& c1, float& c2, float& c3,
                                        uint32_t a0, uint32_t a1, uint32_t a2, uint32_t a3,
                                        uint32_t b0, uint32_t b1) {
    asm volatile(
        "mma.sync.aligned.m16n8k16.row.col.f32.f16.f16.f32 "
        "{%0,%1,%2,%3}, {%4,%5,%6,%7}, {%8,%9}, {%0,%1,%2,%3};"
        : "+f"(c0), "+f"(c1), "+f"(c2), "+f"(c3)
        : "r"(a0), "r"(a1), "r"(a2), "r"(a3), "r"(b0), "r"(b1));
}

// ---------------------------------------------------------------------------
// Kernel 0: one-time W fp32 -> fp16 conversion
// ---------------------------------------------------------------------------
__global__ void __launch_bounds__(256) wconv(const float* __restrict__ w)
{
    int i = blockIdx.x * 256 + threadIdx.x;     // 110592 uint2 outputs
    if (i < 110592) {
        float4 v = ((const float4*)w)[i];
        uint2 o;
        o.x = pack_h2(v.x, v.y);
        o.y = pack_h2(v.z, v.w);
        ((uint2*)g_wh)[i] = o;
    }
}

// ---------------------------------------------------------------------------
// Kernel 1: QKV GEMM, fp16 mma.sync m16n8k16 + ldmatrix fragments.
//   C[128 tokens][1152 ch] = A[m][384] * W^T.
//   As[k][m]: 384 rows x 128 halves, stride 136 halves (272B) -> .trans
//             ldmatrix conflict-free. Prologue is coalesced, no transpose.
//   Bs[n][k]: 128 rows x 32 halves, stride 40 halves (80B) -> conflict-free.
//   2 CTAs/SM; single-buffer stages (2 syncs/stage).
// ---------------------------------------------------------------------------
#define ASTH 136                                   // As row stride (halves)
#define BSTH 40                                    // Bs row stride (halves)
#define AS_BYTES (384 * ASTH * 2)                  // 104,448
#define QKV_SMEM (AS_BYTES + 128 * BSTH * 2)       // 114,688

__global__ void __launch_bounds__(256, 2) qkv_mma(
    const float* __restrict__ x,
    const float* __restrict__ bias)
{
    extern __shared__ char smem[];
    const uint32_t abase = smem_u32(smem);
    const uint32_t bbase = abase + AS_BYTES;

    const int tid = threadIdx.x;
    const int wid = tid >> 5;
    const int lid = tid & 31;
    const int mw  = wid & 1;             // 2 m-subtiles of 64
    const int nw  = wid >> 1;            // 4 n-subtiles of 32
    const int lq  = lid >> 2;            // 0..7
    const int lr  = lid & 3;             // 0..3

    const int m0 = blockIdx.x * 128;     // 50176 % 128 == 0
    const int b  = m0 / HWB;
    const float* xb = x + (size_t)b * C_DIM * HWB + (m0 - b * HWB);

    // ---- Prologue: As[k][m] fp16, coalesced LDG over m, STS.64 ----
    for (int i = tid; i < 12288; i += 256) {       // 384 k x 32 m-quads
        int k = i >> 5, m4 = i & 31;
        float4 v = *(const float4*)(xb + (size_t)k * HWB + m4 * 4);
        uint32_t h0 = pack_h2(v.x, v.y);
        uint32_t h1 = pack_h2(v.z, v.w);
        uint32_t dst = abase + (uint32_t)(k * ASTH + m4 * 4) * 2;
        asm volatile("st.shared.v2.b32 [%0], {%1,%2};" :: "r"(dst), "r"(h0), "r"(h1));
    }

    // Per-lane ldmatrix address components (bytes)
    // A (.trans): row = k-chunk-local (lane&7) + 8*bit4; col = m
    const uint32_t a_lane = (uint32_t)(((lid & 7) + ((lid >> 4) & 1) * 8) * (ASTH * 2)
                                       + (mw * 64 + ((lid >> 3) & 1) * 8) * 2);
    // B (non-trans): row = n; col-block = 8*bit3 halves
    const uint32_t b_lane = (uint32_t)((nw * 32 + ((lid >> 4) & 1) * 8 + (lid & 7)) * (BSTH * 2)
                                       + ((lid >> 3) & 1) * 16);

    // B-stage load mapping: thread -> (n = tid>>1, two 8-half blocks)
    const int bs_n   = tid >> 1;
    const int bs_kb  = (tid & 1) * 2;    // block 0/1 or 2/3

    for (int nt = 0; nt < 9; ++nt) {
        const int n0 = nt * 128;
        float c[4][4][4];
        #pragma unroll
        for (int i = 0; i < 4; ++i)
            #pragma unroll
            for (int j = 0; j < 4; ++j)
                c[i][j][0] = c[i][j][1] = c[i][j][2] = c[i][j][3] = 0.f;

        for (int s = 0; s < 12; ++s) {
            __syncthreads();             // prior-stage readers done
            // ---- Load B stage: 128n x 32k halves from g_wh ----
            {
                const uint4* src = (const uint4*)(g_wh
                    + (size_t)(n0 + bs_n) * 192 + s * 16 + bs_kb * 4);
                uint4 v0 = src[0];
                uint4 v1 = src[1];
                uint32_t dst = bbase + (uint32_t)(bs_n * (BSTH * 2) + bs_kb * 16);
                asm volatile("st.shared.v4.b32 [%0], {%1,%2,%3,%4};"
                             :: "r"(dst), "r"(v0.x), "r"(v0.y), "r"(v0.z), "r"(v0.w));
                asm volatile("st.shared.v4.b32 [%0], {%1,%2,%3,%4};"
                             :: "r"(dst + 16), "r"(v1.x), "r"(v1.y), "r"(v1.z), "r"(v1.w));
            }
            __syncthreads();

            #pragma unroll
            for (int kc = 0; kc < 2; ++kc) {                // 2 chunks of k16
                uint32_t a[4][4], bb[2][4];
                const uint32_t a_base = abase + a_lane
                    + (uint32_t)((s * 32 + kc * 16) * (ASTH * 2));
                #pragma unroll
                for (int i = 0; i < 4; ++i)
                    ldsm_x4_t(a[i][0], a[i][1], a[i][2], a[i][3],
                              a_base + (uint32_t)(i * 32));          // 16 m-halves
                const uint32_t b_base = bbase + b_lane + (uint32_t)(kc * 32);
                #pragma unroll
                for (int jp = 0; jp < 2; ++jp)
                    ldsm_x4(bb[jp][0], bb[jp][1], bb[jp][2], bb[jp][3],
                            b_base + (uint32_t)(jp * 16 * (BSTH * 2)));
                #pragma unroll
                for (int i = 0; i < 4; ++i)
                    #pragma unroll
                    for (int j = 0; j < 4; ++j) {
                        const int jp = j >> 1, lo = (j & 1) * 2;
                        mma_f16(c[i][j][0], c[i][j][1], c[i][j][2], c[i][j][3],
                                a[i][0], a[i][1], a[i][2], a[i][3],
                                bb[jp][lo], bb[jp][lo + 1]);
                    }
            }
        }

        // ---- Epilogue: bias + float2 stores ----
        #pragma unroll
        for (int j = 0; j < 4; ++j) {
            const int gn = n0 + nw * 32 + j * 8 + lr * 2;
            float2 bv = *(const float2*)(bias + gn);
            #pragma unroll
            for (int i = 0; i < 4; ++i) {
                const int gm0 = m0 + mw * 64 + i * 16 + lq;
                float2 v0 = make_float2(c[i][j][0] + bv.x, c[i][j][1] + bv.y);
                float2 v1 = make_float2(c[i][j][2] + bv.x, c[i][j][3] + bv.y);
                *(float2*)(g_qkv + (size_t)gm0 * N_DIM + gn)       = v0;
                *(float2*)(g_qkv + (size_t)(gm0 + 8) * N_DIM + gn) = v1;
            }
        }
    }
}

// ---------------------------------------------------------------------------
// Kernel 2: windowed attention (unchanged from Round 3)
// ---------------------------------------------------------------------------
#define SD   52
#define VST  100
#define SCST 52
#define ATTN_SMEM ((2 * 96 * SD + 52 * VST + 52 * SCST) * sizeof(float))

__global__ void __launch_bounds__(256) attn_kernel(float* __restrict__ out)
{
    extern __shared__ float sm[];
    float* qs = sm;
    float* ks = qs + 96 * SD;
    float* vs = ks + 96 * SD;
    float* sc = vs + 52 * VST;

    const int tid  = threadIdx.x;
    const int win  = blockIdx.x;
    const int head = blockIdx.y;
    const int b    = win >> 10;
    const int wh   = (win >> 5) & 31;
    const int ww   = win & 31;
    const float scale = 0.10206207261596577f;

    for (int e = tid; e < 3 * 96; e += 256) {
        int d = e % 96;
        int p = 49 + e / 96;
        qs[d * SD + p] = 0.f;
        ks[d * SD + p] = 0.f;
    }

    for (int e = tid; e < 49 * 96; e += 256) {
        int d = e % 96;
        int p = e / 96;
        int ph = p / 7;
        int h  = wh * 7 + ph;
        int wc = ww * 7 + (p - ph * 7);
        const float* row = g_qkv + ((size_t)b * HWB + h * W_IMG + wc) * N_DIM + head * HD;
        qs[d * SD + p] = row[d] * scale;
        ks[d * SD + p] = row[C_DIM + d];
        vs[p * VST + d] = row[2 * C_DIM + d];
    }
    __syncthreads();

    if (tid < 169) {
        const int ti = (tid % 13) * 4;
        const int tj = (tid / 13) * 4;
        float acc[4][4] = {};
        for (int d = 0; d < 96; d++) {
            float4 qv = *(const float4*)(qs + d * SD + ti);
            float4 kv = *(const float4*)(ks + d * SD + tj);
            acc[0][0] += qv.x * kv.x; acc[0][1] += qv.x * kv.y;
            acc[0][2] += qv.x * kv.z; acc[0][3] += qv.x * kv.w;
            acc[1][0] += qv.y * kv.x; acc[1][1] += qv.y * kv.y;
            acc[1][2] += qv.y * kv.z; acc[1][3] += qv.y * kv.w;
            acc[2][0] += qv.z * kv.x; acc[2][1] += qv.z * kv.y;
            acc[2][2] += qv.z * kv.z; acc[2][3] += qv.z * kv.w;
            acc[3][0] += qv.w * kv.x; acc[3][1] += qv.w * kv.y;
            acc[3][2] += qv.w * kv.z; acc[3][3] += qv.w * kv.w;
        }
        #pragma unroll
        for (int jj = 0; jj < 4; jj++) {
            float4 v = make_float4(acc[0][jj], acc[1][jj], acc[2][jj], acc[3][jj]);
            *(float4*)(sc + (tj + jj) * SCST + ti) = v;
        }
    }
    __syncthreads();

    if (tid < 49) {
        float mx = -1e30f;
        for (int j = 0; j < 49; j++) mx = fmaxf(mx, sc[j * SCST + tid]);
        float sum = 0.f;
        for (int j = 0; j < 49; j++) {
            float ev = __expf(sc[j * SCST + tid] - mx);
            sc[j * SCST + tid] = ev;
            sum += ev;
        }
        float inv = 1.f / sum;
        for (int j = 0; j < 49; j++) sc[j * SCST + tid] *= inv;
    }
    __syncthreads();

    float* osm = qs;
    for (int tile = tid; tile < 312; tile += 256) {
        int p0 = (tile % 13) * 4;
        int d0 = (tile / 13) * 4;
        float acc[4][4] = {};
        for (int j = 0; j < 49; j++) {
            float4 av = *(const float4*)(sc + j * SCST + p0);
            float4 vv = *(const float4*)(vs + j * VST + d0);
            acc[0][0] += av.x * vv.x; acc[0][1] += av.x * vv.y;
            acc[0][2] += av.x * vv.z; acc[0][3] += av.x * vv.w;
            acc[1][0] += av.y * vv.x; acc[1][1] += av.y * vv.y;
            acc[1][2] += av.y * vv.z; acc[1][3] += av.y * vv.w;
            acc[2][0] += av.z * vv.x; acc[2][1] += av.z * vv.y;
            acc[2][2] += av.z * vv.z; acc[2][3] += av.z * vv.w;
            acc[3][0] += av.w * vv.x; acc[3][1] += av.w * vv.y;
            acc[3][2] += av.w * vv.z; acc[3][3] += av.w * vv.w;
        }
        #pragma unroll
        for (int pp = 0; pp < 4; pp++) {
            if (p0 + pp < 49) {
                float4 o4 = make_float4(acc[pp][0], acc[pp][1], acc[pp][2], acc[pp][3]);
                *(float4*)(osm + (p0 + pp) * VST + d0) = o4;
            }
        }
    }
    __syncthreads();

    for (int e = tid; e < 49 * 96; e += 256) {
        int p = e % 49;
        int d = e / 49;
        int ph = p / 7;
        int h  = wh * 7 + ph;
        int wc = ww * 7 + (p - ph * 7);
        out[(((size_t)b * C_DIM + head * HD + d) * H_IMG + h) * W_IMG + wc] =
            osm[p * VST + d];
    }
}

// ---------------------------------------------------------------------------
extern "C" void kernel_launch(void* const* d_in, const int* in_sizes, int n_in,
                              void* d_out, int out_size)
{
    const float* x    = (const float*)d_in[0];
    const float* w    = (const float*)d_in[1];
    const float* bias = (const float*)d_in[2];
    float* out        = (float*)d_out;

    cudaFuncSetAttribute(qkv_mma, cudaFuncAttributeMaxDynamicSharedMemorySize,
                         (int)QKV_SMEM);
    cudaFuncSetAttribute(attn_kernel, cudaFuncAttributeMaxDynamicSharedMemorySize,
                         (int)ATTN_SMEM);

    wconv<<<432, 256>>>(w);
    qkv_mma<<<M_TOT / 128, 256, QKV_SMEM>>>(x, bias);
    attn_kernel<<<dim3(B_SZ * 32 * 32, NHEADS), 256, ATTN_SMEM>>>(out);
}

// round 7
// speedup vs baseline: 2.5638x; 1.3730x over previous
#include <cuda_runtime.h>
#include <cstdint>

// Problem constants
#define C_DIM   384
#define N_DIM   1152
#define B_SZ    8
#define H_IMG   224
#define W_IMG   224
#define HWB     50176
#define M_TOT   401408
#define HD      96
#define NHEADS  4

// QKV scratch in natural token order: [M_TOT][1152]
__device__ float g_qkv[(size_t)M_TOT * N_DIM];
// Pre-converted W in fp16 (half2 words): [1152][384] halves
__device__ uint32_t g_wh[221184];

__device__ __forceinline__ uint32_t pack_h2(float lo, float hi) {
    uint32_t r;
    asm("cvt.rn.f16x2.f32 %0, %1, %2;" : "=r"(r) : "f"(hi), "f"(lo));
    return r;   // d<15:0> = lo, d<31:16> = hi
}

__device__ __forceinline__ uint32_t smem_u32(const void* p) {
    uint32_t a;
    asm("{ .reg .u64 t; cvta.to.shared.u64 t, %1; cvt.u32.u64 %0, t; }"
        : "=r"(a) : "l"(p));
    return a;
}

__device__ __forceinline__ void ldsm_x4(uint32_t& r0, uint32_t& r1,
                                        uint32_t& r2, uint32_t& r3, uint32_t a) {
    asm volatile("ldmatrix.sync.aligned.m8n8.x4.shared.b16 {%0,%1,%2,%3}, [%4];"
                 : "=r"(r0), "=r"(r1), "=r"(r2), "=r"(r3) : "r"(a));
}
__device__ __forceinline__ void ldsm_x4_t(uint32_t& r0, uint32_t& r1,
                                          uint32_t& r2, uint32_t& r3, uint32_t a) {
    asm volatile("ldmatrix.sync.aligned.m8n8.x4.trans.shared.b16 {%0,%1,%2,%3}, [%4];"
                 : "=r"(r0), "=r"(r1), "=r"(r2), "=r"(r3) : "r"(a));
}

__device__ __forceinline__ void mma_f16(float& c0, float& c1, float& c2, float& c3,
                                        uint32_t a0, uint32_t a1, uint32_t a2, uint32_t a3,
                                        uint32_t b0, uint32_t b1) {
    asm volatile(
        "mma.sync.aligned.m16n8k16.row.col.f32.f16.f16.f32 "
        "{%0,%1,%2,%3}, {%4,%5,%6,%7}, {%8,%9}, {%0,%1,%2,%3};"
        : "+f"(c0), "+f"(c1), "+f"(c2), "+f"(c3)
        : "r"(a0), "r"(a1), "r"(a2), "r"(a3), "r"(b0), "r"(b1));
}

// ---------------------------------------------------------------------------
// Kernel 0: one-time W fp32 -> fp16 conversion
// ---------------------------------------------------------------------------
__global__ void __launch_bounds__(256) wconv(const float* __restrict__ w)
{
    int i = blockIdx.x * 256 + threadIdx.x;
    if (i < 110592) {
        float4 v = ((const float4*)w)[i];
        uint2 o;
        o.x = pack_h2(v.x, v.y);
        o.y = pack_h2(v.z, v.w);
        ((uint2*)g_wh)[i] = o;
    }
}

// ---------------------------------------------------------------------------
// Kernel 1: QKV GEMM (unchanged from Round 6)
// ---------------------------------------------------------------------------
#define ASTH 136
#define BSTH 40
#define AS_BYTES (384 * ASTH * 2)
#define QKV_SMEM (AS_BYTES + 128 * BSTH * 2)

__global__ void __launch_bounds__(256, 2) qkv_mma(
    const float* __restrict__ x,
    const float* __restrict__ bias)
{
    extern __shared__ char smem[];
    const uint32_t abase = smem_u32(smem);
    const uint32_t bbase = abase + AS_BYTES;

    const int tid = threadIdx.x;
    const int wid = tid >> 5;
    const int lid = tid & 31;
    const int mw  = wid & 1;
    const int nw  = wid >> 1;
    const int lq  = lid >> 2;
    const int lr  = lid & 3;

    const int m0 = blockIdx.x * 128;
    const int b  = m0 / HWB;
    const float* xb = x + (size_t)b * C_DIM * HWB + (m0 - b * HWB);

    for (int i = tid; i < 12288; i += 256) {
        int k = i >> 5, m4 = i & 31;
        float4 v = *(const float4*)(xb + (size_t)k * HWB + m4 * 4);
        uint32_t h0 = pack_h2(v.x, v.y);
        uint32_t h1 = pack_h2(v.z, v.w);
        uint32_t dst = abase + (uint32_t)(k * ASTH + m4 * 4) * 2;
        asm volatile("st.shared.v2.b32 [%0], {%1,%2};" :: "r"(dst), "r"(h0), "r"(h1));
    }

    const uint32_t a_lane = (uint32_t)(((lid & 7) + ((lid >> 4) & 1) * 8) * (ASTH * 2)
                                       + (mw * 64 + ((lid >> 3) & 1) * 8) * 2);
    const uint32_t b_lane = (uint32_t)((nw * 32 + ((lid >> 4) & 1) * 8 + (lid & 7)) * (BSTH * 2)
                                       + ((lid >> 3) & 1) * 16);

    const int bs_n  = tid >> 1;
    const int bs_kb = (tid & 1) * 2;

    for (int nt = 0; nt < 9; ++nt) {
        const int n0 = nt * 128;
        float c[4][4][4];
        #pragma unroll
        for (int i = 0; i < 4; ++i)
            #pragma unroll
            for (int j = 0; j < 4; ++j)
                c[i][j][0] = c[i][j][1] = c[i][j][2] = c[i][j][3] = 0.f;

        for (int s = 0; s < 12; ++s) {
            __syncthreads();
            {
                const uint4* src = (const uint4*)(g_wh
                    + (size_t)(n0 + bs_n) * 192 + s * 16 + bs_kb * 4);
                uint4 v0 = src[0];
                uint4 v1 = src[1];
                uint32_t dst = bbase + (uint32_t)(bs_n * (BSTH * 2) + bs_kb * 16);
                asm volatile("st.shared.v4.b32 [%0], {%1,%2,%3,%4};"
                             :: "r"(dst), "r"(v0.x), "r"(v0.y), "r"(v0.z), "r"(v0.w));
                asm volatile("st.shared.v4.b32 [%0], {%1,%2,%3,%4};"
                             :: "r"(dst + 16), "r"(v1.x), "r"(v1.y), "r"(v1.z), "r"(v1.w));
            }
            __syncthreads();

            #pragma unroll
            for (int kc = 0; kc < 2; ++kc) {
                uint32_t a[4][4], bb[2][4];
                const uint32_t a_base = abase + a_lane
                    + (uint32_t)((s * 32 + kc * 16) * (ASTH * 2));
                #pragma unroll
                for (int i = 0; i < 4; ++i)
                    ldsm_x4_t(a[i][0], a[i][1], a[i][2], a[i][3],
                              a_base + (uint32_t)(i * 32));
                const uint32_t b_base = bbase + b_lane + (uint32_t)(kc * 32);
                #pragma unroll
                for (int jp = 0; jp < 2; ++jp)
                    ldsm_x4(bb[jp][0], bb[jp][1], bb[jp][2], bb[jp][3],
                            b_base + (uint32_t)(jp * 16 * (BSTH * 2)));
                #pragma unroll
                for (int i = 0; i < 4; ++i)
                    #pragma unroll
                    for (int j = 0; j < 4; ++j) {
                        const int jp = j >> 1, lo = (j & 1) * 2;
                        mma_f16(c[i][j][0], c[i][j][1], c[i][j][2], c[i][j][3],
                                a[i][0], a[i][1], a[i][2], a[i][3],
                                bb[jp][lo], bb[jp][lo + 1]);
                    }
            }
        }

        #pragma unroll
        for (int j = 0; j < 4; ++j) {
            const int gn = n0 + nw * 32 + j * 8 + lr * 2;
            float2 bv = *(const float2*)(bias + gn);
            #pragma unroll
            for (int i = 0; i < 4; ++i) {
                const int gm0 = m0 + mw * 64 + i * 16 + lq;
                float2 v0 = make_float2(c[i][j][0] + bv.x, c[i][j][1] + bv.y);
                float2 v1 = make_float2(c[i][j][2] + bv.x, c[i][j][3] + bv.y);
                *(float2*)(g_qkv + (size_t)gm0 * N_DIM + gn)       = v0;
                *(float2*)(g_qkv + (size_t)(gm0 + 8) * N_DIM + gn) = v1;
            }
        }
    }
}

// ---------------------------------------------------------------------------
// Kernel 2: tensor-core windowed attention.
//   Block = (window, head), 128 threads, warp = 16-query m-tile.
//   Q/K/V fp16 in SMEM, [row][96] stride 208B (ldmatrix conflict-free).
//   Scores: 8 n-tiles x 6 k -> regs; softmax in regs (quad shfl);
//   attn fp16 packed from score C-regs = A frags of AV; normalize post-AV.
// ---------------------------------------------------------------------------
#define ROWB 208                      // bytes per Q/K/V row (104 halves)
#define MATB (64 * ROWB)              // 13312 bytes per matrix
#define AT_SMEM (3 * MATB)            // 39936

__global__ void __launch_bounds__(128) attn_tc(float* __restrict__ out)
{
    extern __shared__ char smem[];
    const uint32_t qb = smem_u32(smem);
    const uint32_t kb = qb + MATB;
    const uint32_t vb = kb + MATB;
    uint32_t* smw = (uint32_t*)smem;
    float* osm = (float*)smem;        // reused AFTER AV (post-sync)

    const int tid  = threadIdx.x;
    const int wrp  = tid >> 5;
    const int lid  = tid & 31;
    const int lam  = lid & 3;
    const int win  = blockIdx.x;
    const int head = blockIdx.y;
    const int b    = win >> 10;
    const int wh   = (win >> 5) & 31;
    const int ww   = win & 31;

    // Zero pad rows 49..63 of Q/K/V (as 32-bit words; 52 words/row)
    for (int i = tid; i < 2340; i += 128) {
        int arr = i / 780, rem = i % 780;
        smw[arr * 3328 + (49 + rem / 52) * 52 + (rem % 52)] = 0u;
    }

    // Load Q (scaled), K, V: 49 tokens x 24 float4 x 3 segs
    const float scale = 0.10206207261596577f;   // 96^-0.5
    for (int e = tid; e < 3528; e += 128) {
        int tok = e / 72, r = e % 72;
        int seg = r / 24, f4 = r % 24;
        const float* src = g_qkv
            + ((size_t)b * HWB + (wh * 7 + tok / 7) * W_IMG + ww * 7 + tok % 7) * N_DIM
            + seg * C_DIM + head * HD + f4 * 4;
        float4 v = *(const float4*)src;
        if (seg == 0) { v.x *= scale; v.y *= scale; v.z *= scale; v.w *= scale; }
        uint32_t h0 = pack_h2(v.x, v.y), h1 = pack_h2(v.z, v.w);
        uint32_t dst = qb + (uint32_t)(seg * MATB + tok * ROWB + f4 * 8);
        asm volatile("st.shared.v2.b32 [%0], {%1,%2};" :: "r"(dst), "r"(h0), "r"(h1));
    }
    __syncthreads();

    // ---- Scores: S[q][key] = Q . K, 7 n-tiles used (keys 0..55) ----
    const int q0 = wrp * 16;
    const uint32_t a_addr = qb + (uint32_t)((q0 + (lid & 15)) * ROWB + (lid >> 4) * 16);
    const uint32_t k_rsel = (uint32_t)((((lid >> 4) & 1) * 8 + (lid & 7)) * ROWB
                                       + ((lid >> 3) & 1) * 16);
    float sc[7][4];
    #pragma unroll
    for (int t = 0; t < 7; ++t)
        sc[t][0] = sc[t][1] = sc[t][2] = sc[t][3] = 0.f;

    #pragma unroll
    for (int s = 0; s < 6; ++s) {
        uint32_t a0, a1, a2, a3;
        ldsm_x4(a0, a1, a2, a3, a_addr + (uint32_t)(s * 32));
        #pragma unroll
        for (int np = 0; np < 4; ++np) {
            uint32_t r0, r1, r2, r3;
            ldsm_x4(r0, r1, r2, r3, kb + k_rsel + (uint32_t)(np * 16 * ROWB + s * 32));
            mma_f16(sc[2*np][0], sc[2*np][1], sc[2*np][2], sc[2*np][3],
                    a0, a1, a2, a3, r0, r1);
            if (np < 3)
                mma_f16(sc[2*np+1][0], sc[2*np+1][1], sc[2*np+1][2], sc[2*np+1][3],
                        a0, a1, a2, a3, r2, r3);
        }
    }

    // ---- Softmax in registers (rows r = lid>>2 and r+8 of this m-tile) ----
    float mx0 = -1e30f, mx1 = -1e30f;
    #pragma unroll
    for (int t = 0; t < 6; ++t) {
        mx0 = fmaxf(mx0, fmaxf(sc[t][0], sc[t][1]));
        mx1 = fmaxf(mx1, fmaxf(sc[t][2], sc[t][3]));
    }
    if (lam == 0) { mx0 = fmaxf(mx0, sc[6][0]); mx1 = fmaxf(mx1, sc[6][2]); }
    mx0 = fmaxf(mx0, __shfl_xor_sync(0xffffffffu, mx0, 1));
    mx0 = fmaxf(mx0, __shfl_xor_sync(0xffffffffu, mx0, 2));
    mx1 = fmaxf(mx1, __shfl_xor_sync(0xffffffffu, mx1, 1));
    mx1 = fmaxf(mx1, __shfl_xor_sync(0xffffffffu, mx1, 2));

    float pr[7][4];
    float sum0 = 0.f, sum1 = 0.f;
    #pragma unroll
    for (int t = 0; t < 6; ++t) {
        pr[t][0] = __expf(sc[t][0] - mx0);
        pr[t][1] = __expf(sc[t][1] - mx0);
        pr[t][2] = __expf(sc[t][2] - mx1);
        pr[t][3] = __expf(sc[t][3] - mx1);
        sum0 += pr[t][0] + pr[t][1];
        sum1 += pr[t][2] + pr[t][3];
    }
    pr[6][0] = (lam == 0) ? __expf(sc[6][0] - mx0) : 0.f;
    pr[6][1] = 0.f;
    pr[6][2] = (lam == 0) ? __expf(sc[6][2] - mx1) : 0.f;
    pr[6][3] = 0.f;
    sum0 += pr[6][0];
    sum1 += pr[6][2];
    sum0 += __shfl_xor_sync(0xffffffffu, sum0, 1);
    sum0 += __shfl_xor_sync(0xffffffffu, sum0, 2);
    sum1 += __shfl_xor_sync(0xffffffffu, sum1, 1);
    sum1 += __shfl_xor_sync(0xffffffffu, sum1, 2);
    const float inv0 = 1.f / sum0;
    const float inv1 = 1.f / sum1;

    // ---- AV: out = P . V  (P fp16 from regs; normalize after) ----
    float co[12][4];
    #pragma unroll
    for (int t = 0; t < 12; ++t)
        co[t][0] = co[t][1] = co[t][2] = co[t][3] = 0.f;

    const uint32_t v_rsel = (uint32_t)((lid & 15) * ROWB + ((lid >> 4) & 1) * 16);
    #pragma unroll
    for (int t = 0; t < 4; ++t) {
        uint32_t a0 = pack_h2(pr[2*t][0], pr[2*t][1]);
        uint32_t a1 = pack_h2(pr[2*t][2], pr[2*t][3]);
        uint32_t a2 = 0u, a3 = 0u;
        if (t < 3) {
            a2 = pack_h2(pr[2*t+1][0], pr[2*t+1][1]);
            a3 = pack_h2(pr[2*t+1][2], pr[2*t+1][3]);
        }
        #pragma unroll
        for (int np = 0; np < 6; ++np) {
            uint32_t r0, r1, r2, r3;
            ldsm_x4_t(r0, r1, r2, r3, vb + v_rsel + (uint32_t)(t * 16 * ROWB + np * 32));
            mma_f16(co[2*np][0], co[2*np][1], co[2*np][2], co[2*np][3],
                    a0, a1, a2, a3, r0, r1);
            mma_f16(co[2*np+1][0], co[2*np+1][1], co[2*np+1][2], co[2*np+1][3],
                    a0, a1, a2, a3, r2, r3);
        }
    }
    __syncthreads();   // all warps done with Q/K/V smem -> safe to reuse as osm

    // ---- Stage normalized output rows to osm[49][96] ----
    {
        const int r   = lid >> 2;
        const int rg0 = q0 + r;
        const int rg8 = q0 + r + 8;
        #pragma unroll
        for (int nt = 0; nt < 12; ++nt) {
            const int d = nt * 8 + 2 * lam;
            if (rg0 < 49)
                *(float2*)(osm + rg0 * 96 + d) =
                    make_float2(co[nt][0] * inv0, co[nt][1] * inv0);
            if (rg8 < 49)
                *(float2*)(osm + rg8 * 96 + d) =
                    make_float2(co[nt][2] * inv1, co[nt][3] * inv1);
        }
    }
    __syncthreads();

    // ---- Coalesced-ish global write (w-contiguous runs of 7) ----
    for (int e = tid; e < 4704; e += 128) {
        int tok = e % 49, d = e / 49;
        out[(((size_t)b * C_DIM + head * HD + d) * H_IMG + wh * 7 + tok / 7) * W_IMG
            + ww * 7 + tok % 7] = osm[tok * 96 + d];
    }
}

// ---------------------------------------------------------------------------
extern "C" void kernel_launch(void* const* d_in, const int* in_sizes, int n_in,
                              void* d_out, int out_size)
{
    const float* x    = (const float*)d_in[0];
    const float* w    = (const float*)d_in[1];
    const float* bias = (const float*)d_in[2];
    float* out        = (float*)d_out;

    cudaFuncSetAttribute(qkv_mma, cudaFuncAttributeMaxDynamicSharedMemorySize,
                         (int)QKV_SMEM);
    cudaFuncSetAttribute(attn_tc, cudaFuncAttributeMaxDynamicSharedMemorySize,
                         (int)AT_SMEM);

    wconv<<<432, 256>>>(w);
    qkv_mma<<<M_TOT / 128, 256, QKV_SMEM>>>(x, bias);
    attn_tc<<<dim3(B_SZ * 32 * 32, NHEADS), 128, AT_SMEM>>>(out);
}